// round 1
// baseline (speedup 1.0000x reference)
#include <cuda_runtime.h>

#define LSEQ 64
#define HDIM 128
#define PITCH 132   // HDIM + 4 -> conflict-free column-parallel float4 access
#define SPITCH 65   // LSEQ + 1 -> odd pitch, conflict-free rows & columns (scalar)

// Precomputed bilinear form and bias cross-terms (scaled by 1/1024)
__device__ float g_M[HDIM * HDIM];
__device__ float g_u[HDIM];
__device__ float g_v[HDIM];
__device__ float g_s0;

// ---------------------------------------------------------------------------
// Kernel 0: zero the accumulators (atomics accumulate into them each replay)
// ---------------------------------------------------------------------------
__global__ void zero_kernel() {
    int i = blockIdx.x * blockDim.x + threadIdx.x;
    if (i < HDIM * HDIM) g_M[i] = 0.f;
    if (i < HDIM) { g_u[i] = 0.f; g_v[i] = 0.f; }
    if (i == HDIM * HDIM) g_s0 = 0.f;
}

// ---------------------------------------------------------------------------
// Kernel 1: M = W_pep^T @ W_cdr3 / 1024 (+ bias cross terms)
// grid 32 CTAs, CTA g handles k in [32g, 32g+32). 256 threads.
// ---------------------------------------------------------------------------
__global__ void precompute_kernel(const float* __restrict__ Wp,
                                  const float* __restrict__ Wc,
                                  const float* __restrict__ bp,
                                  const float* __restrict__ bc) {
    __shared__ float As[32][HDIM];
    __shared__ float Bs[32][HDIM];
    const int t  = threadIdx.x;
    const int k0 = blockIdx.x * 32;

    // coalesced float4 loads of 32x128 tiles
    const float4* Wp4 = (const float4*)(Wp + (size_t)k0 * HDIM);
    const float4* Wc4 = (const float4*)(Wc + (size_t)k0 * HDIM);
    float4* As4 = (float4*)&As[0][0];
    float4* Bs4 = (float4*)&Bs[0][0];
    for (int i = t; i < 32 * (HDIM / 4); i += 256) { As4[i] = Wp4[i]; Bs4[i] = Wc4[i]; }
    __syncthreads();

    // warp w -> e rows [16w,16w+16), lane l -> d cols [4l,4l+4)
    const int w = t >> 5, l = t & 31;
    const int e0 = w * 16, d0 = l * 4;
    float acc[16][4];
    #pragma unroll
    for (int i = 0; i < 16; i++)
        #pragma unroll
        for (int j = 0; j < 4; j++) acc[i][j] = 0.f;

    #pragma unroll 4
    for (int k = 0; k < 32; k++) {
        float4 b4 = *(const float4*)&Bs[k][d0];
        float bb[4] = {b4.x, b4.y, b4.z, b4.w};
        #pragma unroll
        for (int i = 0; i < 16; i++) {
            float a = As[k][e0 + i];   // broadcast
            #pragma unroll
            for (int j = 0; j < 4; j++) acc[i][j] += a * bb[j];
        }
    }
    const float inv = 1.0f / 1024.0f;
    #pragma unroll
    for (int i = 0; i < 16; i++)
        #pragma unroll
        for (int j = 0; j < 4; j++)
            atomicAdd(&g_M[(e0 + i) * HDIM + d0 + j], acc[i][j] * inv);

    if (t < HDIM) {
        float su = 0.f, sv = 0.f;
        for (int k = 0; k < 32; k++) { su += As[k][t] * bc[k0 + k]; sv += Bs[k][t] * bp[k0 + k]; }
        atomicAdd(&g_u[t], su * inv);
        atomicAdd(&g_v[t], sv * inv);
    }
    if (t == 255) {
        float s = 0.f;
        for (int k = 0; k < 32; k++) s += bp[k0 + k] * bc[k0 + k];
        atomicAdd(&g_s0, s * inv);
    }
}

// ---------------------------------------------------------------------------
// Kernel 2: fused main kernel — one CTA per batch element, 256 threads
// ---------------------------------------------------------------------------
struct SmemMain {
    float Ap[LSEQ][PITCH];     // peptide [p][e]
    float Msh[HDIM][PITCH];    // M [e][d]
    float PM[LSEQ][PITCH];     // pep @ M  [p][d]
    float AcT[HDIM][SPITCH];   // cdr3 transposed [d][c]
    float S[LSEQ][SPITCH];     // scores -> exp(scores - max)
    float pu[LSEQ], cv[LSEQ], RS[LSEQ], CS[LSEQ];
    float red[32];
    float outP[HDIM], outC[HDIM];
    float mx, Z, s0;
};

__global__ void __launch_bounds__(256, 1)
main_kernel(const float* __restrict__ pep, const float* __restrict__ cdr3,
            float* __restrict__ out) {
    extern __shared__ char smem_raw[];
    SmemMain& sm = *(SmemMain*)smem_raw;
    const int t = threadIdx.x;
    const int b = blockIdx.x;
    const int w = t >> 5, l = t & 31;

    // ---- cooperative loads ----
    const float4* pep4 = (const float4*)(pep + (size_t)b * LSEQ * HDIM);
    const float4* cdr4 = (const float4*)(cdr3 + (size_t)b * LSEQ * HDIM);
    const float4* M4   = (const float4*)g_M;

    for (int i = t; i < LSEQ * (HDIM / 4); i += 256) {       // peptide rows
        int r = i >> 5, d4 = i & 31;
        *(float4*)&sm.Ap[r][d4 * 4] = pep4[i];
    }
    for (int i = t; i < HDIM * (HDIM / 4); i += 256) {       // M
        int e = i >> 5, d4 = i & 31;
        *(float4*)&sm.Msh[e][d4 * 4] = M4[i];
    }
    for (int i = t; i < LSEQ * (HDIM / 4); i += 256) {       // cdr3 -> transposed
        int c = i >> 5, d4 = i & 31;
        float4 v = cdr4[i];
        sm.AcT[d4 * 4 + 0][c] = v.x;
        sm.AcT[d4 * 4 + 1][c] = v.y;
        sm.AcT[d4 * 4 + 2][c] = v.z;
        sm.AcT[d4 * 4 + 3][c] = v.w;
    }
    if (t == 0) sm.s0 = g_s0;
    __syncthreads();

    // ---- bias projections (zero in this dataset, kept for generality) ----
    if (t < LSEQ) {
        float s = 0.f;
        for (int e = 0; e < HDIM; e++) s += sm.Ap[t][e] * g_u[e];
        sm.pu[t] = s;
    } else if (t < 2 * LSEQ) {
        int c = t - LSEQ;
        float s = 0.f;
        for (int d = 0; d < HDIM; d++) s += sm.AcT[d][c] * g_v[d];
        sm.cv[c] = s;
    }

    // ---- GEMM1: PM[p][d] = sum_e Ap[p][e] * Msh[e][d] ----
    // warp w -> p in [8w, 8w+8), lane l -> d in [4l, 4l+4)
    {
        const int p0 = w * 8, d0 = l * 4;
        float acc[8][4];
        #pragma unroll
        for (int i = 0; i < 8; i++)
            #pragma unroll
            for (int j = 0; j < 4; j++) acc[i][j] = 0.f;

        for (int e = 0; e < HDIM; e += 4) {
            float mv[4][4];
            #pragma unroll
            for (int q = 0; q < 4; q++) {
                float4 m = *(const float4*)&sm.Msh[e + q][d0];
                mv[q][0] = m.x; mv[q][1] = m.y; mv[q][2] = m.z; mv[q][3] = m.w;
            }
            #pragma unroll
            for (int i = 0; i < 8; i++) {
                float4 a = *(const float4*)&sm.Ap[p0 + i][e];   // broadcast
                float av[4] = {a.x, a.y, a.z, a.w};
                #pragma unroll
                for (int q = 0; q < 4; q++)
                    #pragma unroll
                    for (int j = 0; j < 4; j++) acc[i][j] += av[q] * mv[q][j];
            }
        }
        #pragma unroll
        for (int i = 0; i < 8; i++)
            *(float4*)&sm.PM[p0 + i][d0] =
                make_float4(acc[i][0], acc[i][1], acc[i][2], acc[i][3]);
    }
    __syncthreads();

    // ---- GEMM2: S[p][c] = sum_d PM[p][d] * AcT[d][c] + pu[p] + cv[c] + s0 ----
    // warp w -> p in [8w, 8w+8), lane l -> c in {l, l+32}
    {
        const int p0 = w * 8;
        const float s0v = sm.s0;
        const float cv0 = sm.cv[l], cv1 = sm.cv[l + 32];
        float acc[8][2];
        #pragma unroll
        for (int i = 0; i < 8; i++) {
            float puv = sm.pu[p0 + i];
            acc[i][0] = puv + cv0 + s0v;
            acc[i][1] = puv + cv1 + s0v;
        }
        for (int d = 0; d < HDIM; d += 4) {
            float b0[4], b1[4];
            #pragma unroll
            for (int q = 0; q < 4; q++) {
                b0[q] = sm.AcT[d + q][l];
                b1[q] = sm.AcT[d + q][l + 32];
            }
            #pragma unroll
            for (int i = 0; i < 8; i++) {
                float4 a = *(const float4*)&sm.PM[p0 + i][d];   // broadcast
                float av[4] = {a.x, a.y, a.z, a.w};
                #pragma unroll
                for (int q = 0; q < 4; q++) {
                    acc[i][0] += av[q] * b0[q];
                    acc[i][1] += av[q] * b1[q];
                }
            }
        }
        #pragma unroll
        for (int i = 0; i < 8; i++) {
            sm.S[p0 + i][l]      = acc[i][0];
            sm.S[p0 + i][l + 32] = acc[i][1];
        }
    }
    __syncthreads();

    // ---- softmax over all 4096 scores: max ----
    float m = -1e30f;
    #pragma unroll
    for (int q = 0; q < 16; q++) {
        int f = t * 16 + q;
        m = fmaxf(m, sm.S[f >> 6][f & 63]);
    }
    #pragma unroll
    for (int o = 16; o > 0; o >>= 1) m = fmaxf(m, __shfl_xor_sync(~0u, m, o));
    if (l == 0) sm.red[w] = m;
    __syncthreads();
    if (t == 0) {
        float mm = sm.red[0];
        #pragma unroll
        for (int i = 1; i < 8; i++) mm = fmaxf(mm, sm.red[i]);
        sm.mx = mm;
    }
    __syncthreads();

    // ---- exp in place ----
    const float mx = sm.mx;
    #pragma unroll
    for (int q = 0; q < 16; q++) {
        int f = t * 16 + q;
        float* sp = &sm.S[f >> 6][f & 63];
        *sp = __expf(*sp - mx);
    }
    __syncthreads();

    // ---- row sums (RS, weight cdr3) and column sums (CS, weight peptide) ----
    if (t < LSEQ) {
        float s = 0.f;
        for (int c = 0; c < LSEQ; c++) s += sm.S[t][c];
        sm.RS[t] = s;
    } else if (t < 2 * LSEQ) {
        int c = t - LSEQ;
        float s = 0.f;
        for (int p = 0; p < LSEQ; p++) s += sm.S[p][c];
        sm.CS[c] = s;
    }
    __syncthreads();
    if (t < 32) {
        float z = sm.RS[t] + sm.RS[t + 32];
        #pragma unroll
        for (int o = 16; o > 0; o >>= 1) z += __shfl_xor_sync(~0u, z, o);
        if (t == 0) sm.Z = z;
    }
    __syncthreads();

    // ---- epilogue: out[b,h] = (sum_j pep[j][h]*CS[j] + sum_i cdr3[i][h]*RS[i]) / Z
    if (t < HDIM) {
        const int h = t;
        float s = 0.f;
        for (int j = 0; j < LSEQ; j++) s += sm.Ap[j][h] * sm.CS[j];
        sm.outP[h] = s;
    } else {
        const int h = t - HDIM;
        float s = 0.f;
        for (int i = 0; i < LSEQ; i++) s += sm.AcT[h][i] * sm.RS[i];
        sm.outC[h] = s;
    }
    __syncthreads();
    if (t < HDIM) {
        const float invZ = 1.0f / sm.Z;
        out[(size_t)b * HDIM + t] = (sm.outP[t] + sm.outC[t]) * invZ;
    }
}

// ---------------------------------------------------------------------------
extern "C" void kernel_launch(void* const* d_in, const int* in_sizes, int n_in,
                              void* d_out, int out_size) {
    const float* pep = (const float*)d_in[0];
    const float* cdr = (const float*)d_in[1];
    const float* Wc  = (const float*)d_in[2];
    const float* bc  = (const float*)d_in[3];
    const float* Wp  = (const float*)d_in[4];
    const float* bp  = (const float*)d_in[5];
    float* out = (float*)d_out;

    const int B = in_sizes[0] / (LSEQ * HDIM);   // 256

    cudaFuncSetAttribute(main_kernel, cudaFuncAttributeMaxDynamicSharedMemorySize,
                         (int)sizeof(SmemMain));

    zero_kernel<<<(HDIM * HDIM + 256) / 256 + 1, 256>>>();
    precompute_kernel<<<32, 256>>>(Wp, Wc, bp, bc);
    main_kernel<<<B, 256, sizeof(SmemMain)>>>(pep, cdr, out);
}

// round 3
// speedup vs baseline: 1.1978x; 1.1978x over previous
#include <cuda_runtime.h>

#define LSEQ 64
#define HDIM 128
#define PITCH 132   // HDIM + 4 -> conflict-free column-parallel float4 access
#define SPITCH 65   // LSEQ + 1 -> odd pitch, conflict-free rows & columns

// Precomputed bilinear form and bias cross-terms (scaled by 1/1024).
// Written with plain stores (each element owned by exactly one thread), so no
// zeroing pass is needed and replays are deterministic.
struct Pre {
    float M[HDIM * HDIM];
    float u[HDIM];
    float v[HDIM];
    float s0;
};
__device__ Pre g_pre;

// ---------------------------------------------------------------------------
// Kernel 1: M[e][d] = sum_k Wp[k][e] * Wc[k][d] / 1024  (+ bias cross terms)
// grid 64 CTAs (CTA r owns output rows {2r, 2r+1}), 256 threads.
// No atomics: full K reduction in-CTA, direct stores.
// ---------------------------------------------------------------------------
__global__ void __launch_bounds__(256)
precompute_kernel(const float* __restrict__ Wp,
                  const float* __restrict__ Wc,
                  const float* __restrict__ bp,
                  const float* __restrict__ bc) {
    __shared__ float a[2][HDIM];   // a[j][k] = Wp[k][e0+j]
    const int t  = threadIdx.x;
    const int e0 = blockIdx.x * 2;

    // Stage the two Wp columns (strided gather, tiny).
    if (t < 2 * HDIM) {
        int j = t >> 7, k = t & 127;
        a[j][k] = Wp[(size_t)k * HDIM + e0 + j];
    }
    __syncthreads();

    const int j = t >> 7;          // which of the 2 output rows
    const int d = t & 127;         // output column
    const float* arow = a[j];

    float acc = 0.f;
    #pragma unroll 8
    for (int k = 0; k < HDIM; k++)
        acc += arow[k] * Wc[(size_t)k * HDIM + d];   // coalesced, L2-resident

    const float inv = 1.0f / 1024.0f;
    g_pre.M[(size_t)(e0 + j) * HDIM + d] = acc * inv;

    // bias cross terms: u[e] = Wp[:,e]·bc, v[d] = Wc[:,d]·bp, s0 = bp·bc
    if (t < 2) {
        float s = 0.f;
        for (int k = 0; k < HDIM; k++) s += a[t][k] * bc[k];
        g_pre.u[e0 + t] = s * inv;
    } else if (t < 4) {
        int jj = t - 2;
        float s = 0.f;
        for (int k = 0; k < HDIM; k++) s += Wc[(size_t)k * HDIM + e0 + jj] * bp[k];
        g_pre.v[e0 + jj] = s * inv;
    } else if (t == 4 && blockIdx.x == 0) {
        float s = 0.f;
        for (int k = 0; k < HDIM; k++) s += bp[k] * bc[k];
        g_pre.s0 = s * inv;
    }
}

// ---------------------------------------------------------------------------
// Kernel 2: fused main kernel — one CTA per batch element, 512 threads
// ---------------------------------------------------------------------------
struct SmemMain {
    float Ap[LSEQ][PITCH];     // peptide [p][e]
    float Msh[HDIM][PITCH];    // M [e][d]
    float PM[LSEQ][PITCH];     // pep @ M  [p][d]
    float AcT[HDIM][SPITCH];   // cdr3 transposed [d][c]
    float S[LSEQ][SPITCH];     // scores -> exp(scores - max)
    float pu[LSEQ], cv[LSEQ], RS[LSEQ], CS[LSEQ];
    float red[16];
    float outP[HDIM], outC[HDIM];
    float mx, Z, s0;
};

__global__ void __launch_bounds__(512, 1)
main_kernel(const float* __restrict__ pep, const float* __restrict__ cdr3,
            float* __restrict__ out) {
    extern __shared__ char smem_raw[];
    SmemMain& sm = *(SmemMain*)smem_raw;
    const int t = threadIdx.x;
    const int b = blockIdx.x;
    const int w = t >> 5, l = t & 31;

    // ---- cooperative loads ----
    const float4* pep4 = (const float4*)(pep + (size_t)b * LSEQ * HDIM);
    const float4* cdr4 = (const float4*)(cdr3 + (size_t)b * LSEQ * HDIM);
    const float4* M4   = (const float4*)g_pre.M;

    for (int i = t; i < LSEQ * (HDIM / 4); i += 512) {       // peptide rows
        int r = i >> 5, d4 = i & 31;
        *(float4*)&sm.Ap[r][d4 * 4] = pep4[i];
    }
    for (int i = t; i < HDIM * (HDIM / 4); i += 512) {       // M
        int e = i >> 5, d4 = i & 31;
        *(float4*)&sm.Msh[e][d4 * 4] = M4[i];
    }
    for (int i = t; i < LSEQ * (HDIM / 4); i += 512) {       // cdr3 -> transposed
        int c = i >> 5, d4 = i & 31;
        float4 v = cdr4[i];
        sm.AcT[d4 * 4 + 0][c] = v.x;
        sm.AcT[d4 * 4 + 1][c] = v.y;
        sm.AcT[d4 * 4 + 2][c] = v.z;
        sm.AcT[d4 * 4 + 3][c] = v.w;
    }
    if (t == 0) sm.s0 = g_pre.s0;
    __syncthreads();

    // ---- bias projections (zero in this dataset, kept for generality) ----
    // Run concurrently with GEMM1 (read-only on Ap/AcT); consumed by GEMM2
    // which is after a __syncthreads().
    if (t < LSEQ) {
        float s = 0.f;
        for (int e = 0; e < HDIM; e++) s += sm.Ap[t][e] * g_pre.u[e];
        sm.pu[t] = s;
    } else if (t < 2 * LSEQ) {
        int c = t - LSEQ;
        float s = 0.f;
        for (int d = 0; d < HDIM; d++) s += sm.AcT[d][c] * g_pre.v[d];
        sm.cv[c] = s;
    }

    // ---- GEMM1: PM[p][d] = sum_e Ap[p][e] * Msh[e][d] ----
    // 16 warps: warp w -> p in [4w, 4w+4), lane l -> d in [4l, 4l+4)
    {
        const int p0 = w * 4, d0 = l * 4;
        float acc[4][4];
        #pragma unroll
        for (int i = 0; i < 4; i++)
            #pragma unroll
            for (int j = 0; j < 4; j++) acc[i][j] = 0.f;

        #pragma unroll 2
        for (int e = 0; e < HDIM; e += 4) {
            float mv[4][4];
            #pragma unroll
            for (int q = 0; q < 4; q++) {
                float4 m = *(const float4*)&sm.Msh[e + q][d0];
                mv[q][0] = m.x; mv[q][1] = m.y; mv[q][2] = m.z; mv[q][3] = m.w;
            }
            #pragma unroll
            for (int i = 0; i < 4; i++) {
                float4 a = *(const float4*)&sm.Ap[p0 + i][e];   // broadcast
                float av[4] = {a.x, a.y, a.z, a.w};
                #pragma unroll
                for (int q = 0; q < 4; q++)
                    #pragma unroll
                    for (int j = 0; j < 4; j++) acc[i][j] += av[q] * mv[q][j];
            }
        }
        #pragma unroll
        for (int i = 0; i < 4; i++)
            *(float4*)&sm.PM[p0 + i][d0] =
                make_float4(acc[i][0], acc[i][1], acc[i][2], acc[i][3]);
    }
    __syncthreads();

    // ---- GEMM2: S[p][c] = sum_d PM[p][d] * AcT[d][c] + pu[p] + cv[c] + s0 ----
    // 16 warps: warp w -> p in [4w, 4w+4), lane l -> c in {l, l+32}
    {
        const int p0 = w * 4;
        const float s0v = sm.s0;
        const float cv0 = sm.cv[l], cv1 = sm.cv[l + 32];
        float acc[4][2];
        #pragma unroll
        for (int i = 0; i < 4; i++) {
            float puv = sm.pu[p0 + i];
            acc[i][0] = puv + cv0 + s0v;
            acc[i][1] = puv + cv1 + s0v;
        }
        #pragma unroll 2
        for (int d = 0; d < HDIM; d += 4) {
            float b0[4], b1[4];
            #pragma unroll
            for (int q = 0; q < 4; q++) {
                b0[q] = sm.AcT[d + q][l];
                b1[q] = sm.AcT[d + q][l + 32];
            }
            #pragma unroll
            for (int i = 0; i < 4; i++) {
                float4 a = *(const float4*)&sm.PM[p0 + i][d];   // broadcast
                float av[4] = {a.x, a.y, a.z, a.w};
                #pragma unroll
                for (int q = 0; q < 4; q++) {
                    acc[i][0] += av[q] * b0[q];
                    acc[i][1] += av[q] * b1[q];
                }
            }
        }
        #pragma unroll
        for (int i = 0; i < 4; i++) {
            sm.S[p0 + i][l]      = acc[i][0];
            sm.S[p0 + i][l + 32] = acc[i][1];
        }
    }
    __syncthreads();

    // ---- softmax over all 4096 scores: max ----
    float m = -1e30f;
    #pragma unroll
    for (int q = 0; q < 8; q++) {
        int f = t * 8 + q;
        m = fmaxf(m, sm.S[f >> 6][f & 63]);
    }
    #pragma unroll
    for (int o = 16; o > 0; o >>= 1) m = fmaxf(m, __shfl_xor_sync(~0u, m, o));
    if (l == 0) sm.red[w] = m;
    __syncthreads();
    if (t == 0) {
        float mm = sm.red[0];
        #pragma unroll
        for (int i = 1; i < 16; i++) mm = fmaxf(mm, sm.red[i]);
        sm.mx = mm;
    }
    __syncthreads();

    // ---- exp in place ----
    const float mx = sm.mx;
    #pragma unroll
    for (int q = 0; q < 8; q++) {
        int f = t * 8 + q;
        float* sp = &sm.S[f >> 6][f & 63];
        *sp = __expf(*sp - mx);
    }
    __syncthreads();

    // ---- row sums (RS, weight cdr3) and column sums (CS, weight peptide) ----
    if (t < LSEQ) {
        float s = 0.f;
        for (int c = 0; c < LSEQ; c++) s += sm.S[t][c];
        sm.RS[t] = s;
    } else if (t < 2 * LSEQ) {
        int c = t - LSEQ;
        float s = 0.f;
        for (int p = 0; p < LSEQ; p++) s += sm.S[p][c];
        sm.CS[c] = s;
    }
    __syncthreads();
    if (t < 32) {
        float z = sm.RS[t] + sm.RS[t + 32];
        #pragma unroll
        for (int o = 16; o > 0; o >>= 1) z += __shfl_xor_sync(~0u, z, o);
        if (t == 0) sm.Z = z;
    }
    __syncthreads();

    // ---- epilogue: out[b,h] = (sum_j pep[j][h]*CS[j] + sum_i cdr3[i][h]*RS[i]) / Z
    if (t < HDIM) {
        const int h = t;
        float s = 0.f;
        for (int j = 0; j < LSEQ; j++) s += sm.Ap[j][h] * sm.CS[j];
        sm.outP[h] = s;
    } else if (t < 2 * HDIM) {
        const int h = t - HDIM;
        float s = 0.f;
        for (int i = 0; i < LSEQ; i++) s += sm.AcT[h][i] * sm.RS[i];
        sm.outC[h] = s;
    }
    __syncthreads();
    if (t < HDIM) {
        const float invZ = 1.0f / sm.Z;
        out[(size_t)b * HDIM + t] = (sm.outP[t] + sm.outC[t]) * invZ;
    }
}

// ---------------------------------------------------------------------------
extern "C" void kernel_launch(void* const* d_in, const int* in_sizes, int n_in,
                              void* d_out, int out_size) {
    const float* pep = (const float*)d_in[0];
    const float* cdr = (const float*)d_in[1];
    const float* Wc  = (const float*)d_in[2];
    const float* bc  = (const float*)d_in[3];
    const float* Wp  = (const float*)d_in[4];
    const float* bp  = (const float*)d_in[5];
    float* out = (float*)d_out;

    const int B = in_sizes[0] / (LSEQ * HDIM);   // 256

    cudaFuncSetAttribute(main_kernel, cudaFuncAttributeMaxDynamicSharedMemorySize,
                         (int)sizeof(SmemMain));

    precompute_kernel<<<64, 256>>>(Wp, Wc, bp, bc);
    main_kernel<<<B, 512, sizeof(SmemMain)>>>(pep, cdr, out);
}